// round 6
// baseline (speedup 1.0000x reference)
#include <cuda_runtime.h>
#include <math.h>
#include <stdint.h>

#define BSZ 512
#define ZD  256
#define KK2 512                 // concat K for GEMM (h|s vs w|a)
#define REC_BLOCKS 512
#define TI 16                   // i-values per pm block
#define JCHUNKS 16
#define JC (BSZ / JCHUNKS)      // 32
#define SPLITK 8
#define KSP (KK2 / SPLITK)      // 64
#define GBK 32
#define LOG2PI_F 1.8378770664093453f
#define LOG2E_F  1.4426950408889634f

typedef unsigned long long u64;

// ---------------- scratch ----------------------------------------------------
__device__ float g_wa[BSZ * KK2];     // [j][0:256)=w=exp(lv), [256:512)=a=mu*w
__device__ float g_hs[BSZ * KK2];     // [i][0:256)=-0.5*lat^2, [256:512)=lat
__device__ float g_w2[BSZ * ZD];      // w * log2e    (pm)
__device__ float g_a2[BSZ * ZD];      // a * log2e    (pm)
__device__ float g_c2[BSZ * ZD];      // c * log2e    (pm)
__device__ float g_Crow[BSZ];
__device__ float g_dwkl[BSZ];
__device__ float g_recb[REC_BLOCKS];
__device__ float g_tc[BSZ];
__device__ float g_log_norm;
__device__ unsigned int g_ctr;
__device__ float g_M[SPLITK][BSZ * BSZ];     // GEMM split-K partials (8MB)
__device__ float g_S[JCHUNKS][BSZ * ZD];     // pm partial sums (8MB)

// ---------------- packed f32x2 helpers ---------------------------------------
__device__ __forceinline__ u64 pk2(float lo, float hi) {
    u64 r; asm("mov.b64 %0,{%1,%2};" : "=l"(r) : "f"(lo), "f"(hi)); return r;
}
__device__ __forceinline__ void upk2(u64 v, float& lo, float& hi) {
    asm("mov.b64 {%0,%1},%2;" : "=f"(lo), "=f"(hi) : "l"(v));
}
__device__ __forceinline__ u64 fma2(u64 a, u64 b, u64 c) {
    u64 d; asm("fma.rn.f32x2 %0,%1,%2,%3;" : "=l"(d) : "l"(a), "l"(b), "l"(c)); return d;
}
__device__ __forceinline__ u64 add2(u64 a, u64 b) {
    u64 d; asm("add.rn.f32x2 %0,%1,%2;" : "=l"(d) : "l"(a), "l"(b)); return d;
}
__device__ __forceinline__ u64 mul2(u64 a, u64 b) {
    u64 d; asm("mul.rn.f32x2 %0,%1,%2;" : "=l"(d) : "l"(a), "l"(b)); return d;
}
__device__ __forceinline__ float ex2f(float x) {
    float y; asm("ex2.approx.f32 %0,%1;" : "=f"(y) : "f"(x)); return y;
}

// packed exp2 via FMA-pipe polynomial (deg-5, rel err ~2.4e-6); x <= ~0
__device__ __forceinline__ u64 exp2_poly2(u64 x) {
    const u64 MAGIC2  = pk2( 12582912.0f,  12582912.0f);
    const u64 NMAGIC2 = pk2(-12582912.0f, -12582912.0f);
    const u64 NEG1    = pk2(-1.0f, -1.0f);
    const u64 C0 = pk2(1.0f, 1.0f);
    const u64 C1 = pk2(0.69314718f,  0.69314718f);
    const u64 C2 = pk2(0.24022650f,  0.24022650f);
    const u64 C3 = pk2(0.055504110f, 0.055504110f);
    const u64 C4 = pk2(0.0096181291f, 0.0096181291f);
    const u64 C5 = pk2(0.0013333558f, 0.0013333558f);
    u64 tt = add2(x, MAGIC2);
    u64 tm = add2(tt, NMAGIC2);
    u64 r  = fma2(tm, NEG1, x);
    u64 rr = mul2(r, r);
    u64 A  = fma2(r, C1, C0);
    u64 B  = fma2(r, C3, C2);
    u64 Cc = fma2(r, C5, C4);
    u64 D  = fma2(rr, Cc, B);
    u64 E  = fma2(rr, D, A);               // 2^frac
    int tlo = (int)tt;
    int thi = (int)(tt >> 32);
    float nlo = __int_as_float((tlo << 23) + 0x3F800000);   // 2^n
    float nhi = __int_as_float((thi << 23) + 0x3F800000);
    return mul2(E, pk2(nlo, nhi));
}

// ---------------- reductions --------------------------------------------------
__device__ __forceinline__ float warp_sum(float v) {
#pragma unroll
    for (int o = 16; o; o >>= 1) v += __shfl_xor_sync(0xffffffffu, v, o);
    return v;
}
__device__ __forceinline__ float warp_max(float v) {
#pragma unroll
    for (int o = 16; o; o >>= 1) v = fmaxf(v, __shfl_xor_sync(0xffffffffu, v, o));
    return v;
}
__device__ __forceinline__ float block_sum_256(float v, float* sh) {
    int lane = threadIdx.x & 31, w = threadIdx.x >> 5;
    v = warp_sum(v);
    if (lane == 0) sh[w] = v;
    __syncthreads();
    float r = (threadIdx.x < 8) ? sh[threadIdx.x] : 0.0f;
    if (w == 0) r = warp_sum(r);
    __syncthreads();
    return r;
}
__device__ __forceinline__ float block_max_256(float v, float* sh) {
    int lane = threadIdx.x & 31, w = threadIdx.x >> 5;
    v = warp_max(v);
    if (lane == 0) sh[w] = v;
    __syncthreads();
    float r = (threadIdx.x < 8) ? sh[threadIdx.x] : -INFINITY;
    if (w == 0) r = warp_max(r);
    __syncthreads();
    return r;
}

// ---------------- FMA-pipe natural log -----------------------------------------
__device__ __forceinline__ float fast_log(float x) {
    int ix = __float_as_int(x);
    int e  = (ix - 0x3f3504f3) >> 23;
    float m = __int_as_float(ix - (e << 23));
    float f = m - 1.0f;
    float z = f * f;
    float y = 7.0376836292e-2f;
    y = fmaf(y, f, -1.1514610310e-1f);
    y = fmaf(y, f,  1.1676998740e-1f);
    y = fmaf(y, f, -1.2420140846e-1f);
    y = fmaf(y, f,  1.4249322787e-1f);
    y = fmaf(y, f, -1.6668057665e-1f);
    y = fmaf(y, f,  2.0000714765e-1f);
    y = fmaf(y, f, -2.4999993993e-1f);
    y = fmaf(y, f,  3.3333331174e-1f);
    y = y * f * z;
    float ef = (float)e;
    y = fmaf(ef, -2.12194440e-4f, y);
    y = fmaf(-0.5f, z, y);
    float r = f + y;
    return fmaf(ef, 0.693359375f, r);
}

// ================= kernel 1: fused precompute (128 blocks x 4 rows) =============
__global__ void __launch_bounds__(256) prep_kernel(const float* __restrict__ mu,
                                                   const float* __restrict__ logvar,
                                                   const float* __restrict__ lat,
                                                   const void* __restrict__ dsz) {
    __shared__ float sh[4][8];
    __shared__ float sh2[4][8];
    int b = blockIdx.x;
    int t = threadIdx.x;
    int lane = t & 31, wp = t >> 5;

    float cs[4], ds[4];
#pragma unroll
    for (int r = 0; r < 4; r++) {
        int j = b * 4 + r;
        int idx = j * ZD + t;
        float lv = logvar[idx];
        float m  = mu[idx];
        float w  = __expf(lv);
        float a  = m * w;
        float c  = -0.5f * (fmaf(m * m, w, lv) + LOG2PI_F);
        g_wa[j * KK2 + t]      = w;
        g_wa[j * KK2 + ZD + t] = a;
        g_w2[idx] = w * LOG2E_F;
        g_a2[idx] = a * LOG2E_F;
        g_c2[idx] = c * LOG2E_F;
        float v = lat[idx];
        g_hs[j * KK2 + t]      = -0.5f * v * v;
        g_hs[j * KK2 + ZD + t] = v;
        cs[r] = c;
        ds[r] = fmaf(0.5f, __expf(lv + m * m), fmaf(-0.5f, lv, -0.5f));
    }

#pragma unroll
    for (int r = 0; r < 4; r++) {
        float a = warp_sum(cs[r]);
        float d = warp_sum(ds[r]);
        if (lane == 0) { sh[r][wp] = a; sh2[r][wp] = d; }
    }
    __syncthreads();
    if (t < 4) {
        float ct = 0.0f, dt = 0.0f;
#pragma unroll
        for (int q = 0; q < 8; q++) { ct += sh[t][q]; dt += sh2[t][q]; }
        g_Crow[b * 4 + t] = ct;
        g_dwkl[b * 4 + t] = dt;
    }

    if (b == 0 && t == 0) {
        int   iv = ((const int*)dsz)[0];
        float fv = ((const float*)dsz)[0];
        float ds_val = (iv > 0 && iv < 1073741824) ? (float)iv : fv;
        g_log_norm = logf((float)BSZ) + logf(ds_val);
        g_ctr = 0;
    }
}

// ================= mega-kernel bodies ===========================================
__device__ void gemm_body(int idx, float* As, float* Bs) {
    int tid = threadIdx.x;
    int kb  = (idx >> 6) * KSP;
    int rem = idx & 63;
    int j0  = (rem & 7) * 64;
    int i0  = (rem >> 3) * 64;
    int tx = tid & 15, ty = tid >> 4;

    float acc[4][4];
#pragma unroll
    for (int r = 0; r < 4; r++)
#pragma unroll
        for (int c = 0; c < 4; c++) acc[r][c] = 0.0f;

#pragma unroll
    for (int kc = 0; kc < KSP; kc += GBK) {
#pragma unroll
        for (int p = 0; p < 2; p++) {
            int q   = tid + p * 256;
            int row = q >> 3;
            int k4  = (q & 7) * 4;
            float4 va = *(const float4*)&g_hs[(i0 + row) * KK2 + kb + kc + k4];
            float4 vb = *(const float4*)&g_wa[(j0 + row) * KK2 + kb + kc + k4];
            As[(k4 + 0) * 68 + row] = va.x;
            As[(k4 + 1) * 68 + row] = va.y;
            As[(k4 + 2) * 68 + row] = va.z;
            As[(k4 + 3) * 68 + row] = va.w;
            Bs[(k4 + 0) * 68 + row] = vb.x;
            Bs[(k4 + 1) * 68 + row] = vb.y;
            Bs[(k4 + 2) * 68 + row] = vb.z;
            Bs[(k4 + 3) * 68 + row] = vb.w;
        }
        __syncthreads();
#pragma unroll 8
        for (int kk = 0; kk < GBK; kk++) {
            float4 av = *(const float4*)&As[kk * 68 + ty * 4];
            float4 bv = *(const float4*)&Bs[kk * 68 + tx * 4];
            acc[0][0] = fmaf(av.x, bv.x, acc[0][0]);
            acc[0][1] = fmaf(av.x, bv.y, acc[0][1]);
            acc[0][2] = fmaf(av.x, bv.z, acc[0][2]);
            acc[0][3] = fmaf(av.x, bv.w, acc[0][3]);
            acc[1][0] = fmaf(av.y, bv.x, acc[1][0]);
            acc[1][1] = fmaf(av.y, bv.y, acc[1][1]);
            acc[1][2] = fmaf(av.y, bv.z, acc[1][2]);
            acc[1][3] = fmaf(av.y, bv.w, acc[1][3]);
            acc[2][0] = fmaf(av.z, bv.x, acc[2][0]);
            acc[2][1] = fmaf(av.z, bv.y, acc[2][1]);
            acc[2][2] = fmaf(av.z, bv.z, acc[2][2]);
            acc[2][3] = fmaf(av.z, bv.w, acc[2][3]);
            acc[3][0] = fmaf(av.w, bv.x, acc[3][0]);
            acc[3][1] = fmaf(av.w, bv.y, acc[3][1]);
            acc[3][2] = fmaf(av.w, bv.z, acc[3][2]);
            acc[3][3] = fmaf(av.w, bv.w, acc[3][3]);
        }
        __syncthreads();
    }

    float* out = g_M[idx >> 6];
#pragma unroll
    for (int r = 0; r < 4; r++) {
        float4 v = make_float4(acc[r][0], acc[r][1], acc[r][2], acc[r][3]);
        *(float4*)&out[(i0 + ty * 4 + r) * BSZ + j0 + tx * 4] = v;
    }
}

__device__ void pm_body(int idx, const float* __restrict__ lat) {
    int jc = idx & (JCHUNKS - 1);
    int i0 = (idx >> 4) * TI;
    int t  = threadIdx.x;

    u64 s2[TI / 2], h2[TI / 2], acc[TI / 2];
#pragma unroll
    for (int p = 0; p < TI / 2; p++) {
        float v0 = lat[(i0 + 2 * p) * ZD + t];
        float v1 = lat[(i0 + 2 * p + 1) * ZD + t];
        s2[p]  = pk2(v0 * LOG2E_F, v1 * LOG2E_F);
        h2[p]  = pk2(-0.5f * v0 * v0, -0.5f * v1 * v1);
        acc[p] = 0ULL;
    }

    const float* wp = g_w2 + jc * JC * ZD + t;
    const float* ap = g_a2 + jc * JC * ZD + t;
    const float* cp = g_c2 + jc * JC * ZD + t;

    // per-j pipe alternation: even j -> FMA-pipe poly exp2, odd j -> MUFU ex2.
    // Balances fma pipe (also carrying gemm) against MUFU (also carrying rec).
#pragma unroll 2
    for (int j = 0; j < JC; j += 2) {
        {   // even j: polynomial path
            float w = wp[j * ZD], a = ap[j * ZD], c = cp[j * ZD];
            u64 w2 = pk2(w, w), a2 = pk2(a, a), c2 = pk2(c, c);
#pragma unroll
            for (int p = 0; p < TI / 2; p++) {
                u64 x = fma2(h2[p], w2, fma2(s2[p], a2, c2));
                acc[p] = add2(acc[p], exp2_poly2(x));
            }
        }
        {   // odd j: MUFU path
            float w = wp[(j + 1) * ZD], a = ap[(j + 1) * ZD], c = cp[(j + 1) * ZD];
            u64 w2 = pk2(w, w), a2 = pk2(a, a), c2 = pk2(c, c);
#pragma unroll
            for (int p = 0; p < TI / 2; p++) {
                u64 x = fma2(h2[p], w2, fma2(s2[p], a2, c2));
                float xlo, xhi;
                upk2(x, xlo, xhi);
                acc[p] = add2(acc[p], pk2(ex2f(xlo), ex2f(xhi)));
            }
        }
    }

#pragma unroll
    for (int p = 0; p < TI / 2; p++) {
        float a0, a1;
        upk2(acc[p], a0, a1);
        g_S[jc][(i0 + 2 * p) * ZD + t]     = a0;
        g_S[jc][(i0 + 2 * p + 1) * ZD + t] = a1;
    }
}

__device__ void rec_body(int idx, const float* __restrict__ data,
                         const float* __restrict__ recon, int n4, float* sh) {
    const float4* d4 = (const float4*)data;
    const float4* r4 = (const float4*)recon;
    float acc = 0.0f;
    for (int i = idx * 256 + threadIdx.x; i < n4; i += REC_BLOCKS * 256) {
        float4 d = d4[i];
        float4 r = r4[i];
        acc += d.x * __logf(r.x) + (1.0f - d.x) * __logf(1.0f - r.x);
        acc += d.y * __logf(r.y) + (1.0f - d.y) * __logf(1.0f - r.y);
        acc += d.z * __logf(r.z) + (1.0f - d.z) * __logf(1.0f - r.z);
        acc += d.w * __logf(r.w) + (1.0f - d.w) * __logf(1.0f - r.w);
    }
    float s = block_sum_256(acc, sh);
    if (threadIdx.x == 0) g_recb[idx] = s;
}

// ================= kernel 2: heterogeneous mega-kernel ===========================
__global__ void __launch_bounds__(256, 3) mega_kernel(const float* __restrict__ data,
                                                      const float* __restrict__ recon,
                                                      const float* __restrict__ lat,
                                                      int n4) {
    __shared__ float smem[2 * GBK * 68];
    int bx = blockIdx.x;
    int type = bx % 3;
    int idx  = bx / 3;
    if (type == 0) {
        gemm_body(idx, smem, smem + GBK * 68);
    } else if (type == 1) {
        pm_body(idx, lat);
    } else {
        rec_body(idx, data, recon, n4, smem);
    }
}

// ================= kernel 3: epilogue (lse + pm_log + last-block final) ==========
__global__ void __launch_bounds__(256) epi_kernel(float* __restrict__ out) {
    __shared__ float sh[8];
    __shared__ float smx;
    __shared__ bool s_last;
    int i = blockIdx.x, t = threadIdx.x;

    // --- logqz: LSE over j of row-sum matrix ---
    float v0 = g_Crow[t];
    float v1 = g_Crow[t + 256];
#pragma unroll
    for (int z = 0; z < SPLITK; z++) {
        v0 += g_M[z][i * BSZ + t];
        v1 += g_M[z][i * BSZ + t + 256];
    }
    float mx = block_max_256(fmaxf(v0, v1), sh);
    if (t == 0) smx = mx;
    __syncthreads();
    mx = smx;
    float se = __expf(v0 - mx) + __expf(v1 - mx);
    se = block_sum_256(se, sh);
    float logqz = mx + __logf(se) - g_log_norm;   // valid in t==0

    // --- pm: sum_k log(sum over chunks) ---
    int idx = i * ZD + t;
    float S = 0.0f;
#pragma unroll
    for (int jc = 0; jc < JCHUNKS; jc++) S += g_S[jc][idx];
    float v = fast_log(S);
    float tot = block_sum_256(v, sh);

    if (t == 0) {
        float pm = tot - (float)ZD * g_log_norm;
        g_tc[i] = logqz - pm;
        __threadfence();
        unsigned int prev = atomicAdd(&g_ctr, 1u);
        s_last = (prev == BSZ - 1);
    }
    __syncthreads();

    if (s_last) {
        float rec = 0.0f;
        for (int b = t; b < REC_BLOCKS; b += 256) rec += g_recb[b];
        float dw = 0.0f, tc = 0.0f;
        for (int b = t; b < BSZ; b += 256) {
            dw += g_dwkl[b];
            tc += g_tc[b];
        }
        rec = block_sum_256(rec, sh);
        dw  = block_sum_256(dw,  sh);
        tc  = block_sum_256(tc,  sh);
        if (t == 0) out[0] = (tc + dw - rec) * (1.0f / (float)BSZ);
    }
}

// ---------------- launch ----------------------------------------------------------
extern "C" void kernel_launch(void* const* d_in, const int* in_sizes, int n_in,
                              void* d_out, int out_size) {
    const float* data   = (const float*)d_in[0];
    const float* recon  = (const float*)d_in[1];
    const float* latent = (const float*)d_in[2];
    const float* mu     = (const float*)d_in[3];
    const float* logvar = (const float*)d_in[4];
    const void*  dsz    = d_in[5];

    int n4 = in_sizes[0] / 4;

    prep_kernel<<<BSZ / 4, 256>>>(mu, logvar, latent, dsz);
    mega_kernel<<<1536, 256>>>(data, recon, latent, n4);
    epi_kernel<<<BSZ, 256>>>((float*)d_out);
}

// round 7
// speedup vs baseline: 1.1020x; 1.1020x over previous
#include <cuda_runtime.h>
#include <math.h>
#include <stdint.h>

#define BSZ 512
#define ZD  256
#define KK2 512                 // concat K for GEMM (h|s vs w|a)
#define REC_BLOCKS 512
#define TI 16                   // i-values per pm block
#define JCHUNKS 16
#define JC (BSZ / JCHUNKS)      // 32
#define SPLITK 8
#define KSP (KK2 / SPLITK)      // 64
#define GBK 32
#define LOG2PI_F 1.8378770664093453f
#define LOG2E_F  1.4426950408889634f

typedef unsigned long long u64;

// ---------------- scratch ----------------------------------------------------
__device__ float g_Crow[BSZ];
__device__ float g_dwkl[BSZ];
__device__ float g_recb[REC_BLOCKS];
__device__ float g_tc[BSZ];
__device__ unsigned int g_ctr;               // zero-init; epi resets it each run
__device__ float g_M[SPLITK][BSZ * BSZ];     // GEMM split-K partials (8MB)
__device__ float g_S[JCHUNKS][BSZ * ZD];     // pm partial sums (8MB)

// ---------------- packed f32x2 helpers ---------------------------------------
__device__ __forceinline__ u64 pk2(float lo, float hi) {
    u64 r; asm("mov.b64 %0,{%1,%2};" : "=l"(r) : "f"(lo), "f"(hi)); return r;
}
__device__ __forceinline__ void upk2(u64 v, float& lo, float& hi) {
    asm("mov.b64 {%0,%1},%2;" : "=f"(lo), "=f"(hi) : "l"(v));
}
__device__ __forceinline__ u64 fma2(u64 a, u64 b, u64 c) {
    u64 d; asm("fma.rn.f32x2 %0,%1,%2,%3;" : "=l"(d) : "l"(a), "l"(b), "l"(c)); return d;
}
__device__ __forceinline__ u64 add2(u64 a, u64 b) {
    u64 d; asm("add.rn.f32x2 %0,%1,%2;" : "=l"(d) : "l"(a), "l"(b)); return d;
}
__device__ __forceinline__ u64 mul2(u64 a, u64 b) {
    u64 d; asm("mul.rn.f32x2 %0,%1,%2;" : "=l"(d) : "l"(a), "l"(b)); return d;
}
__device__ __forceinline__ float ex2f(float x) {
    float y; asm("ex2.approx.f32 %0,%1;" : "=f"(y) : "f"(x)); return y;
}

// packed exp2 via FMA-pipe polynomial (deg-5, rel err ~2.4e-6); x <= ~0
__device__ __forceinline__ u64 exp2_poly2(u64 x) {
    const u64 MAGIC2  = pk2( 12582912.0f,  12582912.0f);
    const u64 NMAGIC2 = pk2(-12582912.0f, -12582912.0f);
    const u64 NEG1    = pk2(-1.0f, -1.0f);
    const u64 C0 = pk2(1.0f, 1.0f);
    const u64 C1 = pk2(0.69314718f,  0.69314718f);
    const u64 C2 = pk2(0.24022650f,  0.24022650f);
    const u64 C3 = pk2(0.055504110f, 0.055504110f);
    const u64 C4 = pk2(0.0096181291f, 0.0096181291f);
    const u64 C5 = pk2(0.0013333558f, 0.0013333558f);
    u64 tt = add2(x, MAGIC2);
    u64 tm = add2(tt, NMAGIC2);
    u64 r  = fma2(tm, NEG1, x);
    u64 rr = mul2(r, r);
    u64 A  = fma2(r, C1, C0);
    u64 B  = fma2(r, C3, C2);
    u64 Cc = fma2(r, C5, C4);
    u64 D  = fma2(rr, Cc, B);
    u64 E  = fma2(rr, D, A);               // 2^frac
    int tlo = (int)tt;
    int thi = (int)(tt >> 32);
    float nlo = __int_as_float((tlo << 23) + 0x3F800000);   // 2^n
    float nhi = __int_as_float((thi << 23) + 0x3F800000);
    return mul2(E, pk2(nlo, nhi));
}

// ---------------- reductions --------------------------------------------------
__device__ __forceinline__ float warp_sum(float v) {
#pragma unroll
    for (int o = 16; o; o >>= 1) v += __shfl_xor_sync(0xffffffffu, v, o);
    return v;
}
__device__ __forceinline__ float warp_max(float v) {
#pragma unroll
    for (int o = 16; o; o >>= 1) v = fmaxf(v, __shfl_xor_sync(0xffffffffu, v, o));
    return v;
}
__device__ __forceinline__ float block_sum_256(float v, float* sh) {
    int lane = threadIdx.x & 31, w = threadIdx.x >> 5;
    v = warp_sum(v);
    if (lane == 0) sh[w] = v;
    __syncthreads();
    float r = (threadIdx.x < 8) ? sh[threadIdx.x] : 0.0f;
    if (w == 0) r = warp_sum(r);
    __syncthreads();
    return r;
}
__device__ __forceinline__ float block_max_256(float v, float* sh) {
    int lane = threadIdx.x & 31, w = threadIdx.x >> 5;
    v = warp_max(v);
    if (lane == 0) sh[w] = v;
    __syncthreads();
    float r = (threadIdx.x < 8) ? sh[threadIdx.x] : -INFINITY;
    if (w == 0) r = warp_max(r);
    __syncthreads();
    return r;
}

// ---------------- FMA-pipe natural log -----------------------------------------
__device__ __forceinline__ float fast_log(float x) {
    int ix = __float_as_int(x);
    int e  = (ix - 0x3f3504f3) >> 23;
    float m = __int_as_float(ix - (e << 23));
    float f = m - 1.0f;
    float z = f * f;
    float y = 7.0376836292e-2f;
    y = fmaf(y, f, -1.1514610310e-1f);
    y = fmaf(y, f,  1.1676998740e-1f);
    y = fmaf(y, f, -1.2420140846e-1f);
    y = fmaf(y, f,  1.4249322787e-1f);
    y = fmaf(y, f, -1.6668057665e-1f);
    y = fmaf(y, f,  2.0000714765e-1f);
    y = fmaf(y, f, -2.4999993993e-1f);
    y = fmaf(y, f,  3.3333331174e-1f);
    y = y * f * z;
    float ef = (float)e;
    y = fmaf(ef, -2.12194440e-4f, y);
    y = fmaf(-0.5f, z, y);
    float r = f + y;
    return fmaf(ef, 0.693359375f, r);
}

// ================= mega-kernel bodies ===========================================
// GEMM over concat features: A[i][k] = k<256 ? -0.5*lat^2 : lat
//                            B[j][k] = k<256 ? exp(lv)    : mu*exp(lv)
// computed on the fly from the raw inputs during the smem tile load.
__device__ void gemm_body(int idx, float* As, float* Bs,
                          const float* __restrict__ lat,
                          const float* __restrict__ mu,
                          const float* __restrict__ logvar) {
    int tid = threadIdx.x;
    int kb  = (idx >> 6) * KSP;
    int rem = idx & 63;
    int j0  = (rem & 7) * 64;
    int i0  = (rem >> 3) * 64;
    int tx = tid & 15, ty = tid >> 4;
    bool first_half = (kb < ZD);     // whole 64-wide k-slice lies in one half

    float acc[4][4];
#pragma unroll
    for (int r = 0; r < 4; r++)
#pragma unroll
        for (int c = 0; c < 4; c++) acc[r][c] = 0.0f;

#pragma unroll
    for (int kc = 0; kc < KSP; kc += GBK) {
#pragma unroll
        for (int p = 0; p < 2; p++) {
            int q   = tid + p * 256;
            int row = q >> 3;
            int k4  = (q & 7) * 4;
            int gk  = (kb + kc + k4) & (ZD - 1);      // column within the half
            float4 vl = *(const float4*)&lat[(i0 + row) * ZD + gk];
            float4 va, vb;
            if (first_half) {
                va = make_float4(-0.5f * vl.x * vl.x, -0.5f * vl.y * vl.y,
                                 -0.5f * vl.z * vl.z, -0.5f * vl.w * vl.w);
                float4 lv = *(const float4*)&logvar[(j0 + row) * ZD + gk];
                vb = make_float4(__expf(lv.x), __expf(lv.y),
                                 __expf(lv.z), __expf(lv.w));
            } else {
                va = vl;
                float4 lv = *(const float4*)&logvar[(j0 + row) * ZD + gk];
                float4 mm = *(const float4*)&mu[(j0 + row) * ZD + gk];
                vb = make_float4(mm.x * __expf(lv.x), mm.y * __expf(lv.y),
                                 mm.z * __expf(lv.z), mm.w * __expf(lv.w));
            }
            As[(k4 + 0) * 68 + row] = va.x;
            As[(k4 + 1) * 68 + row] = va.y;
            As[(k4 + 2) * 68 + row] = va.z;
            As[(k4 + 3) * 68 + row] = va.w;
            Bs[(k4 + 0) * 68 + row] = vb.x;
            Bs[(k4 + 1) * 68 + row] = vb.y;
            Bs[(k4 + 2) * 68 + row] = vb.z;
            Bs[(k4 + 3) * 68 + row] = vb.w;
        }
        __syncthreads();
#pragma unroll 8
        for (int kk = 0; kk < GBK; kk++) {
            float4 av = *(const float4*)&As[kk * 68 + ty * 4];
            float4 bv = *(const float4*)&Bs[kk * 68 + tx * 4];
            acc[0][0] = fmaf(av.x, bv.x, acc[0][0]);
            acc[0][1] = fmaf(av.x, bv.y, acc[0][1]);
            acc[0][2] = fmaf(av.x, bv.z, acc[0][2]);
            acc[0][3] = fmaf(av.x, bv.w, acc[0][3]);
            acc[1][0] = fmaf(av.y, bv.x, acc[1][0]);
            acc[1][1] = fmaf(av.y, bv.y, acc[1][1]);
            acc[1][2] = fmaf(av.y, bv.z, acc[1][2]);
            acc[1][3] = fmaf(av.y, bv.w, acc[1][3]);
            acc[2][0] = fmaf(av.z, bv.x, acc[2][0]);
            acc[2][1] = fmaf(av.z, bv.y, acc[2][1]);
            acc[2][2] = fmaf(av.z, bv.z, acc[2][2]);
            acc[2][3] = fmaf(av.z, bv.w, acc[2][3]);
            acc[3][0] = fmaf(av.w, bv.x, acc[3][0]);
            acc[3][1] = fmaf(av.w, bv.y, acc[3][1]);
            acc[3][2] = fmaf(av.w, bv.z, acc[3][2]);
            acc[3][3] = fmaf(av.w, bv.w, acc[3][3]);
        }
        __syncthreads();
    }

    float* out = g_M[idx >> 6];
#pragma unroll
    for (int r = 0; r < 4; r++) {
        float4 v = make_float4(acc[r][0], acc[r][1], acc[r][2], acc[r][3]);
        *(float4*)&out[(i0 + ty * 4 + r) * BSZ + j0 + tx * 4] = v;
    }
}

// pm: R5's proven split (pair 0 poly on fma pipe, pairs 1..7 MUFU).
// w2/a2/c2 recomputed on the fly from logvar/mu.
__device__ void pm_body(int idx, const float* __restrict__ lat,
                        const float* __restrict__ mu,
                        const float* __restrict__ logvar) {
    int jc = idx & (JCHUNKS - 1);
    int i0 = (idx >> 4) * TI;
    int t  = threadIdx.x;

    u64 s2[TI / 2], h2[TI / 2], acc[TI / 2];
#pragma unroll
    for (int p = 0; p < TI / 2; p++) {
        float v0 = lat[(i0 + 2 * p) * ZD + t];
        float v1 = lat[(i0 + 2 * p + 1) * ZD + t];
        s2[p]  = pk2(v0 * LOG2E_F, v1 * LOG2E_F);
        h2[p]  = pk2(-0.5f * v0 * v0, -0.5f * v1 * v1);
        acc[p] = 0ULL;
    }

    int jbase = jc * JC;

#pragma unroll 2
    for (int j = 0; j < JC; j++) {
        int off = (jbase + j) * ZD + t;
        float lv = logvar[off];
        float m  = mu[off];
        float w  = __expf(lv);
        float w2v = w * LOG2E_F;
        float a2v = m * w2v;
        float c2v = -0.5f * LOG2E_F * (fmaf(m * m, w, lv) + LOG2PI_F);
        u64 w2 = pk2(w2v, w2v), a2 = pk2(a2v, a2v), c2 = pk2(c2v, c2v);

        // pair 0: FMA-pipe polynomial exp2
        {
            u64 x = fma2(h2[0], w2, fma2(s2[0], a2, c2));
            acc[0] = add2(acc[0], exp2_poly2(x));
        }
        // pairs 1..7: MUFU ex2
#pragma unroll
        for (int p = 1; p < TI / 2; p++) {
            u64 x = fma2(h2[p], w2, fma2(s2[p], a2, c2));
            float xlo, xhi;
            upk2(x, xlo, xhi);
            acc[p] = add2(acc[p], pk2(ex2f(xlo), ex2f(xhi)));
        }
    }

#pragma unroll
    for (int p = 0; p < TI / 2; p++) {
        float a0, a1;
        upk2(acc[p], a0, a1);
        g_S[jc][(i0 + 2 * p) * ZD + t]     = a0;
        g_S[jc][(i0 + 2 * p + 1) * ZD + t] = a1;
    }
}

// rec: BCE partial sum; each rec block also produces Crow[j]/dwkl[j] for j = idx.
__device__ void rec_body(int idx, const float* __restrict__ data,
                         const float* __restrict__ recon, int n4, float* sh,
                         const float* __restrict__ mu,
                         const float* __restrict__ logvar) {
    int t = threadIdx.x;

    // Crow / dwkl for row j = idx
    {
        int off = idx * ZD + t;
        float lv = logvar[off];
        float m  = mu[off];
        float w  = __expf(lv);
        float c  = -0.5f * (fmaf(m * m, w, lv) + LOG2PI_F);
        float dw = fmaf(0.5f, __expf(lv + m * m), fmaf(-0.5f, lv, -0.5f));
        float cs = block_sum_256(c, sh);
        if (t == 0) g_Crow[idx] = cs;
        float ds = block_sum_256(dw, sh);
        if (t == 0) g_dwkl[idx] = ds;
    }

    const float4* d4 = (const float4*)data;
    const float4* r4 = (const float4*)recon;
    float acc = 0.0f;
    for (int i = idx * 256 + t; i < n4; i += REC_BLOCKS * 256) {
        float4 d = d4[i];
        float4 r = r4[i];
        acc += d.x * __logf(r.x) + (1.0f - d.x) * __logf(1.0f - r.x);
        acc += d.y * __logf(r.y) + (1.0f - d.y) * __logf(1.0f - r.y);
        acc += d.z * __logf(r.z) + (1.0f - d.z) * __logf(1.0f - r.z);
        acc += d.w * __logf(r.w) + (1.0f - d.w) * __logf(1.0f - r.w);
    }
    float s = block_sum_256(acc, sh);
    if (t == 0) g_recb[idx] = s;
}

// ================= kernel 1: heterogeneous mega-kernel ===========================
__global__ void __launch_bounds__(256, 3) mega_kernel(const float* __restrict__ data,
                                                      const float* __restrict__ recon,
                                                      const float* __restrict__ lat,
                                                      const float* __restrict__ mu,
                                                      const float* __restrict__ logvar,
                                                      int n4) {
    __shared__ float smem[2 * GBK * 68];
    int bx = blockIdx.x;
    int type = bx % 3;
    int idx  = bx / 3;
    if (type == 0) {
        gemm_body(idx, smem, smem + GBK * 68, lat, mu, logvar);
    } else if (type == 1) {
        pm_body(idx, lat, mu, logvar);
    } else {
        rec_body(idx, data, recon, n4, smem, mu, logvar);
    }
}

// ================= kernel 2: epilogue (lse + pm_log + last-block final) ==========
__global__ void __launch_bounds__(256) epi_kernel(float* __restrict__ out,
                                                  const void* __restrict__ dsz) {
    __shared__ float sh[8];
    __shared__ float smx;
    __shared__ bool s_last;
    int i = blockIdx.x, t = threadIdx.x;

    // log_norm computed locally (uniform; 2 logf per thread, negligible)
    int   iv = ((const int*)dsz)[0];
    float fv = ((const float*)dsz)[0];
    float ds_val = (iv > 0 && iv < 1073741824) ? (float)iv : fv;
    float log_norm = logf((float)BSZ) + logf(ds_val);

    // --- logqz: LSE over j of row-sum matrix ---
    float v0 = g_Crow[t];
    float v1 = g_Crow[t + 256];
#pragma unroll
    for (int z = 0; z < SPLITK; z++) {
        v0 += g_M[z][i * BSZ + t];
        v1 += g_M[z][i * BSZ + t + 256];
    }
    float mx = block_max_256(fmaxf(v0, v1), sh);
    if (t == 0) smx = mx;
    __syncthreads();
    mx = smx;
    float se = __expf(v0 - mx) + __expf(v1 - mx);
    se = block_sum_256(se, sh);
    float logqz = mx + __logf(se) - log_norm;     // valid in t==0

    // --- pm: sum_k log(sum over chunks) ---
    int idx = i * ZD + t;
    float S = 0.0f;
#pragma unroll
    for (int jc = 0; jc < JCHUNKS; jc++) S += g_S[jc][idx];
    float v = fast_log(S);
    float tot = block_sum_256(v, sh);

    if (t == 0) {
        float pm = tot - (float)ZD * log_norm;
        g_tc[i] = logqz - pm;
        __threadfence();
        unsigned int prev = atomicAdd(&g_ctr, 1u);
        s_last = (prev == BSZ - 1);
    }
    __syncthreads();

    if (s_last) {
        float rec = 0.0f;
        for (int b = t; b < REC_BLOCKS; b += 256) rec += g_recb[b];
        float dw = 0.0f, tc = 0.0f;
        for (int b = t; b < BSZ; b += 256) {
            dw += g_dwkl[b];
            tc += g_tc[b];
        }
        rec = block_sum_256(rec, sh);
        dw  = block_sum_256(dw,  sh);
        tc  = block_sum_256(tc,  sh);
        if (t == 0) {
            out[0] = (tc + dw - rec) * (1.0f / (float)BSZ);
            g_ctr = 0;                 // reset for next graph replay
        }
    }
}

// ---------------- launch ----------------------------------------------------------
extern "C" void kernel_launch(void* const* d_in, const int* in_sizes, int n_in,
                              void* d_out, int out_size) {
    const float* data   = (const float*)d_in[0];
    const float* recon  = (const float*)d_in[1];
    const float* latent = (const float*)d_in[2];
    const float* mu     = (const float*)d_in[3];
    const float* logvar = (const float*)d_in[4];
    const void*  dsz    = d_in[5];

    int n4 = in_sizes[0] / 4;

    mega_kernel<<<1536, 256>>>(data, recon, latent, mu, logvar, n4);
    epi_kernel<<<BSZ, 256>>>((float*)d_out, dsz);
}